// round 13
// baseline (speedup 1.0000x reference)
#include <cuda_runtime.h>

// SNN: T=512, B=64, I=1024, H=4096, O=1024, alpha=beta=0.9, thresh=1.0
// GEMM2: fp32, splitK=2 (chunks of 512), ascending FMA chain within chunk,
//        partials combined in order  (CONFIRMED bit-exact, R11/R12)
// GEMM3: fp32, splitK=8 (chunks of 512), same structure (candidate:
//        cuBLASLt heuristic -> 16 tiles x 8 splits = 128 CTAs, chunk=512
//        matching GEMM2's chunk size)
#define Tn 512
#define Bn 64
#define In 1024
#define Hn 4096
#define On 1024

#define NCTA 128
#define NTHR 256
#define NTOT (NCTA * NTHR)

// ---------------- persistent device state ----------------
__device__ float g_s1[Bn * In], g_m1[Bn * In], g_spk1[Bn * In];
__device__ float g_s2[Bn * Hn], g_m2[Bn * Hn], g_spk2[Bn * Hn];
__device__ float g_s3[Bn * On], g_m3[Bn * On];
__device__ float g_w1t[In * Hn];   // w1 transposed (exact copy): [I][H]
__device__ float g_w2t[Hn * On];   // w2 transposed (exact copy): [H][O]
__device__ unsigned g_cnt, g_gen;

// ---------------- grid-wide barrier ----------------
__device__ __forceinline__ void gridbar() {
    __syncthreads();
    if (threadIdx.x == 0) {
        __threadfence();
        unsigned gen = *(volatile unsigned*)&g_gen;
        if (atomicAdd(&g_cnt, 1u) == (unsigned)(NCTA - 1)) {
            g_cnt = 0;
            __threadfence();
            atomicAdd(&g_gen, 1u);
        } else {
            while (*(volatile unsigned*)&g_gen == gen) { __nanosleep(64); }
        }
        __threadfence();
    }
    __syncthreads();
}

// packed f32x2 FMA: two independent fp32 FMAs, bit-identical to scalar FFMA
#define FMA2(d, a, b) asm("fma.rn.f32x2 %0, %1, %2, %0;" : "+l"(d) : "l"(a), "l"(b))

// neuron update (style proven irrelevant: R4 == R7 bit-identical)
__device__ __forceinline__ float neuron_step(float* __restrict__ S,
                                             float* __restrict__ M,
                                             size_t idx, float inp) {
    float s = S[idx], m = M[idx];
    float r = (m > 1.0f) ? 1.0f : 0.0f;
    s = __fmaf_rn(0.9f, s, inp);
    m = __fsub_rn(__fmaf_rn(0.9f, m, s), r);
    S[idx] = s; M[idx] = m;
    return (m > 1.0f) ? 1.0f : 0.0f;
}

// ---------------- GEMM2 (splitK=2) + layer-2 neurons ----------------
// CTA tile: 32 h x 64 b. warp wid owns b [wid*8, wid*8+8); lane tx owns h0+tx.
__device__ __forceinline__ void gemm2_neuron(float (*s_w)[66], float (*s_s)[68]) {
    const int h0  = blockIdx.x * 32;
    const int tx  = threadIdx.x & 31;
    const int wid = threadIdx.x >> 5;

    unsigned long long acc0[4] = {0ull, 0ull, 0ull, 0ull};
    unsigned long long acc1[4] = {0ull, 0ull, 0ull, 0ull};

    for (int kb = 0; kb < In; kb += 32) {
        // stage W chunk [32k][32h], duplicated into f32x2 lanes
        {
            int r = threadIdx.x >> 3, c = threadIdx.x & 7;
            float4 v = *(const float4*)(g_w1t + (size_t)(kb + r) * Hn + h0 + c * 4);
            float2 d;
            d.x = v.x; d.y = v.x; *(float2*)(&s_w[r][(c * 4 + 0) * 2]) = d;
            d.x = v.y; d.y = v.y; *(float2*)(&s_w[r][(c * 4 + 1) * 2]) = d;
            d.x = v.z; d.y = v.z; *(float2*)(&s_w[r][(c * 4 + 2) * 2]) = d;
            d.x = v.w; d.y = v.w; *(float2*)(&s_w[r][(c * 4 + 3) * 2]) = d;
        }
        // stage spikes [32k][64b]
        {
            int b = threadIdx.x & 63, kq = threadIdx.x >> 6;  // kq in [0,4)
            const float* p = g_spk1 + (size_t)b * In + kb + kq * 8;
            float4 v0 = __ldcv((const float4*)p);
            float4 v1 = __ldcv((const float4*)(p + 4));
            s_s[kq * 8 + 0][b] = v0.x;  s_s[kq * 8 + 1][b] = v0.y;
            s_s[kq * 8 + 2][b] = v0.z;  s_s[kq * 8 + 3][b] = v0.w;
            s_s[kq * 8 + 4][b] = v1.x;  s_s[kq * 8 + 5][b] = v1.y;
            s_s[kq * 8 + 6][b] = v1.z;  s_s[kq * 8 + 7][b] = v1.w;
        }
        __syncthreads();
        unsigned long long* acc = (kb < 512) ? acc0 : acc1;
#pragma unroll 8
        for (int kk = 0; kk < 32; kk++) {
            unsigned long long w = *(const unsigned long long*)(&s_w[kk][tx * 2]);
            ulonglong2 sA = *(const ulonglong2*)(&s_s[kk][wid * 8]);
            ulonglong2 sB = *(const ulonglong2*)(&s_s[kk][wid * 8 + 4]);
            FMA2(acc[0], sA.x, w);
            FMA2(acc[1], sA.y, w);
            FMA2(acc[2], sB.x, w);
            FMA2(acc[3], sB.y, w);
        }
        __syncthreads();
    }
    const int h = h0 + tx;
#pragma unroll
    for (int j = 0; j < 4; j++) {
        float2 p0 = *(float2*)(&acc0[j]);
        float2 p1 = *(float2*)(&acc1[j]);
        float cx = __fadd_rn(p0.x, p1.x);
        float cy = __fadd_rn(p0.y, p1.y);
        size_t i0 = (size_t)(wid * 8 + 2 * j) * Hn + h;
        size_t i1 = i0 + Hn;
        g_spk2[i0] = neuron_step(g_s2, g_m2, i0, cx);
        g_spk2[i1] = neuron_step(g_s2, g_m2, i1, cy);
    }
}

// ---------------- GEMM3 (splitK=8, chunk 512) + layer-3 neurons ----------------
// CTA tile: 32 o x 16 b. warp wid owns b-pair (bq + wid*2); lane tx owns o0+tx.
__device__ __forceinline__ void gemm3_neuron(float* __restrict__ out, int t,
                                             float (*s_w)[66], float (*s_s)[68]) {
    const int o0  = (blockIdx.x & 31) * 32;
    const int bq  = (blockIdx.x >> 5) * 16;
    const int tx  = threadIdx.x & 31;
    const int wid = threadIdx.x >> 5;

    unsigned long long part = 0ull;
    float2 tot; tot.x = 0.0f; tot.y = 0.0f;

    for (int kb = 0; kb < Hn; kb += 32) {
        {
            int r = threadIdx.x >> 3, c = threadIdx.x & 7;
            float4 v = *(const float4*)(g_w2t + (size_t)(kb + r) * On + o0 + c * 4);
            float2 d;
            d.x = v.x; d.y = v.x; *(float2*)(&s_w[r][(c * 4 + 0) * 2]) = d;
            d.x = v.y; d.y = v.y; *(float2*)(&s_w[r][(c * 4 + 1) * 2]) = d;
            d.x = v.z; d.y = v.z; *(float2*)(&s_w[r][(c * 4 + 2) * 2]) = d;
            d.x = v.w; d.y = v.w; *(float2*)(&s_w[r][(c * 4 + 3) * 2]) = d;
        }
        if (threadIdx.x < 128) {
            int b = threadIdx.x & 15, kq = threadIdx.x >> 4;  // kq in [0,8)
            float4 v = __ldcv((const float4*)(g_spk2 + (size_t)(bq + b) * Hn + kb + kq * 4));
            s_s[kq * 4 + 0][b] = v.x;  s_s[kq * 4 + 1][b] = v.y;
            s_s[kq * 4 + 2][b] = v.z;  s_s[kq * 4 + 3][b] = v.w;
        }
        __syncthreads();
#pragma unroll 8
        for (int kk = 0; kk < 32; kk++) {
            unsigned long long w  = *(const unsigned long long*)(&s_w[kk][tx * 2]);
            unsigned long long sp = *(const unsigned long long*)(&s_s[kk][wid * 2]);
            FMA2(part, sp, w);
        }
        __syncthreads();
        // end of a 512-k split chunk: fold partial into running total, in order
        if (((kb + 32) & 511) == 0) {
            float2 p = *(float2*)(&part);
            tot.x = __fadd_rn(tot.x, p.x);
            tot.y = __fadd_rn(tot.y, p.y);
            part = 0ull;
        }
    }
    const int o  = o0 + tx;
    const int b0 = bq + wid * 2;
    size_t i0 = (size_t)b0 * On + o;
    size_t i1 = i0 + On;
    float* ot = out + (size_t)t * Bn * On;
    ot[i0] = neuron_step(g_s3, g_m3, i0, tot.x);
    ot[i1] = neuron_step(g_s3, g_m3, i1, tot.y);
}

// ---------------- layer-1 neurons ----------------
__device__ __forceinline__ void phaseA(const float* __restrict__ x, int t, int gt) {
    const float* xt = x + (size_t)t * Bn * In;
    for (int i = gt; i < Bn * In; i += NTOT)
        g_spk1[i] = neuron_step(g_s1, g_m1, i, xt[i]);
}

// ---------------- persistent kernel ----------------
__global__ void __launch_bounds__(NTHR, 1)
snn_kernel(const float* __restrict__ x, const float* __restrict__ w1,
           const float* __restrict__ w2, float* __restrict__ out) {
    __shared__ float s_w[32][66];   // duplicated weight pairs
    __shared__ float s_s[32][68];   // spikes [k][b]
    const int gt = blockIdx.x * NTHR + threadIdx.x;

    for (int i = gt; i < Bn * In; i += NTOT) { g_s1[i] = 0.0f; g_m1[i] = 0.0f; }
    for (int i = gt; i < Bn * Hn; i += NTOT) { g_s2[i] = 0.0f; g_m2[i] = 0.0f; }
    for (int i = gt; i < Bn * On; i += NTOT) { g_s3[i] = 0.0f; g_m3[i] = 0.0f; }
    for (int e = gt; e < In * Hn; e += NTOT) {
        int k = e >> 12, h = e & (Hn - 1);
        g_w1t[e] = w1[(size_t)h * In + k];
    }
    for (int e = gt; e < Hn * On; e += NTOT) {
        int k = e >> 10, o = e & (On - 1);
        g_w2t[e] = w2[(size_t)o * Hn + k];
    }
    gridbar();

    phaseA(x, 0, gt);
    gridbar();

    for (int t = 0; t < Tn; t++) {
        gemm2_neuron(s_w, s_s);
        gridbar();
        gemm3_neuron(out, t, s_w, s_s);
        if (t + 1 < Tn) phaseA(x, t + 1, gt);
        gridbar();
    }
}

extern "C" void kernel_launch(void* const* d_in, const int* in_sizes, int n_in,
                              void* d_out, int out_size) {
    const float* x  = (const float*)d_in[0];   // [512,64,1024]
    const float* w1 = (const float*)d_in[1];   // [4096,1024]
    const float* w2 = (const float*)d_in[2];   // [1024,4096]
    float* out = (float*)d_out;                // [512,64,1024]
    snn_kernel<<<NCTA, NTHR>>>(x, w1, w2, out);
}

// round 14
// speedup vs baseline: 3.4407x; 3.4407x over previous
#include <cuda_runtime.h>

// SNN: T=512, B=64, I=1024, H=4096, O=1024, alpha=beta=0.9, thresh=1.0
// Bit-exact reference arithmetic (proven R13):
//   GEMM2: splitK=2  (512-chunks), ascending fp32 FMA chain, combine ascending
//   GEMM3: splitK=8  (512-chunks), same
// This round: chunk-parallel restructure -> FMA2-pipe-bound GEMM phases.
#define Tn 512
#define Bn 64
#define In 1024
#define Hn 4096
#define On 1024

#define NCTA 128
#define NTHR 256
#define NTOT (NCTA * NTHR)

#define KBLK 16
#define WROW 64
#define SROW 132

// ---------------- persistent device state ----------------
__device__ float g_s1[Bn * In], g_m1[Bn * In], g_spk1[Bn * In];
__device__ float g_s2[Bn * Hn], g_m2[Bn * Hn], g_spk2[Bn * Hn];
__device__ float g_s3[Bn * On], g_m3[Bn * On];
__device__ float g_w1t[In * Hn];   // w1 transposed: [k][h]
__device__ float g_w2t[Hn * On];   // w2 transposed: [k][o]
__device__ float g_p2[2][Bn * Hn]; // GEMM2 chunk partials
__device__ float g_p3[8][Bn * On]; // GEMM3 chunk partials
__device__ unsigned g_cnt, g_gen;

// ---------------- grid-wide barrier (proven R13) ----------------
__device__ __forceinline__ void gridbar() {
    __syncthreads();
    if (threadIdx.x == 0) {
        __threadfence();
        unsigned gen = *(volatile unsigned*)&g_gen;
        if (atomicAdd(&g_cnt, 1u) == (unsigned)(NCTA - 1)) {
            g_cnt = 0;
            __threadfence();
            atomicAdd(&g_gen, 1u);
        } else {
            while (*(volatile unsigned*)&g_gen == gen) { __nanosleep(64); }
        }
        __threadfence();
    }
    __syncthreads();
}

// packed f32x2 FMA: two independent fp32 FMAs, bit-identical to scalar FFMA
#define FMA2(d, a, b) asm("fma.rn.f32x2 %0, %1, %2, %0;" : "+l"(d) : "l"(a), "l"(b))

__device__ __forceinline__ float neuron_step(float* __restrict__ S,
                                             float* __restrict__ M,
                                             size_t idx, float inp) {
    float s = S[idx], m = M[idx];
    float r = (m > 1.0f) ? 1.0f : 0.0f;
    s = __fmaf_rn(0.9f, s, inp);
    m = __fsub_rn(__fmaf_rn(0.9f, m, s), r);
    S[idx] = s; M[idx] = m;
    return (m > 1.0f) ? 1.0f : 0.0f;
}

// ---------------- one 512-k chunk of a GEMM, one CTA ----------------
// part[b][n] (64 b x 64 n at n0) += fold_{k=k0}^{k0+512} spk[b][k]*wT[k][n],
// single fp32 accumulator per element, strictly ascending k (bit-exact).
// Thread: 4 b x 4 n (8 f32x2 chains). Double-buffered smem staging.
template<int KDIM, int NDIM>
__device__ __forceinline__ void gemm_chunk(const float* __restrict__ wT,
                                           const float* __restrict__ spk,
                                           float* __restrict__ part,
                                           int n0, int k0,
                                           float* __restrict__ w_s,
                                           float* __restrict__ s_d) {
    const int tid = threadIdx.x;
    const int hg  = tid & 15;         // n-group (4 n)
    const int b0  = (tid >> 4) * 4;   // first of 4 b
    const int wr  = tid >> 4, wc = tid & 15;  // w staging: k-row, float4-col
    const int sb  = tid >> 2, sk = tid & 3;   // s staging: b, k-quad

    unsigned long long acc[4][2];
#pragma unroll
    for (int i = 0; i < 4; i++) { acc[i][0] = 0ull; acc[i][1] = 0ull; }

    float4 wv, sv;
    // prologue: fetch + stage block 0
    wv = *(const float4*)(wT + (size_t)(k0 + wr) * NDIM + n0 + wc * 4);
    sv = __ldcv((const float4*)(spk + (size_t)sb * KDIM + k0 + sk * 4));
    {
        *(float4*)(w_s + wr * WROW + wc * 4) = wv;
        float2 d;
        d.x = sv.x; d.y = sv.x; *(float2*)(s_d + (sk * 4 + 0) * SROW + 2 * sb) = d;
        d.x = sv.y; d.y = sv.y; *(float2*)(s_d + (sk * 4 + 1) * SROW + 2 * sb) = d;
        d.x = sv.z; d.y = sv.z; *(float2*)(s_d + (sk * 4 + 2) * SROW + 2 * sb) = d;
        d.x = sv.w; d.y = sv.w; *(float2*)(s_d + (sk * 4 + 3) * SROW + 2 * sb) = d;
    }
    __syncthreads();

    int buf = 0;
#pragma unroll 1
    for (int blk = 0; blk < 512 / KBLK; blk++) {
        const bool more = (blk + 1 < 512 / KBLK);
        if (more) {  // prefetch next block into registers
            int kb = k0 + (blk + 1) * KBLK;
            wv = *(const float4*)(wT + (size_t)(kb + wr) * NDIM + n0 + wc * 4);
            sv = __ldcv((const float4*)(spk + (size_t)sb * KDIM + kb + sk * 4));
        }
        const float* wb = w_s + buf * (KBLK * WROW);
        const float* sd = s_d + buf * (KBLK * SROW);
#pragma unroll
        for (int kk = 0; kk < KBLK; kk++) {
            ulonglong2 w2 = *(const ulonglong2*)(wb + kk * WROW + hg * 4);
            ulonglong2 sA = *(const ulonglong2*)(sd + kk * SROW + b0 * 2);
            ulonglong2 sB = *(const ulonglong2*)(sd + kk * SROW + b0 * 2 + 4);
            FMA2(acc[0][0], sA.x, w2.x); FMA2(acc[0][1], sA.x, w2.y);
            FMA2(acc[1][0], sA.y, w2.x); FMA2(acc[1][1], sA.y, w2.y);
            FMA2(acc[2][0], sB.x, w2.x); FMA2(acc[2][1], sB.x, w2.y);
            FMA2(acc[3][0], sB.y, w2.x); FMA2(acc[3][1], sB.y, w2.y);
        }
        if (more) {  // stage prefetched block into alternate buffer
            const int nb = buf ^ 1;
            *(float4*)(w_s + nb * (KBLK * WROW) + wr * WROW + wc * 4) = wv;
            float* sd2 = s_d + nb * (KBLK * SROW);
            float2 d;
            d.x = sv.x; d.y = sv.x; *(float2*)(sd2 + (sk * 4 + 0) * SROW + 2 * sb) = d;
            d.x = sv.y; d.y = sv.y; *(float2*)(sd2 + (sk * 4 + 1) * SROW + 2 * sb) = d;
            d.x = sv.z; d.y = sv.z; *(float2*)(sd2 + (sk * 4 + 2) * SROW + 2 * sb) = d;
            d.x = sv.w; d.y = sv.w; *(float2*)(sd2 + (sk * 4 + 3) * SROW + 2 * sb) = d;
        }
        __syncthreads();
        buf ^= 1;
    }
    // write chunk partials
#pragma unroll
    for (int i = 0; i < 4; i++) {
        float2 a = *(float2*)&acc[i][0];
        float2 b = *(float2*)&acc[i][1];
        float4 o; o.x = a.x; o.y = a.y; o.z = b.x; o.w = b.y;
        *(float4*)(part + (size_t)(b0 + i) * NDIM + n0 + hg * 4) = o;
    }
}

// ---------------- elementwise phases ----------------
__device__ __forceinline__ void phaseA(const float* __restrict__ x, int t, int gt) {
    const float* xt = x + (size_t)t * Bn * In;
    for (int i = gt; i < Bn * In; i += NTOT)
        g_spk1[i] = neuron_step(g_s1, g_m1, i, xt[i]);
}

__device__ __forceinline__ void phaseL2(int gt) {
    for (int i = gt; i < Bn * Hn; i += NTOT) {
        float cur = __fadd_rn(__ldcv(&g_p2[0][i]), __ldcv(&g_p2[1][i]));
        g_spk2[i] = neuron_step(g_s2, g_m2, i, cur);
    }
}

__device__ __forceinline__ void phaseL3(float* __restrict__ out, int t, int gt) {
    float* ot = out + (size_t)t * Bn * On;
    for (int i = gt; i < Bn * On; i += NTOT) {
        float cur = __ldcv(&g_p3[0][i]);
#pragma unroll
        for (int c = 1; c < 8; c++) cur = __fadd_rn(cur, __ldcv(&g_p3[c][i]));
        ot[i] = neuron_step(g_s3, g_m3, i, cur);
    }
}

// ---------------- persistent kernel ----------------
__global__ void __launch_bounds__(NTHR, 1)
snn_kernel(const float* __restrict__ x, const float* __restrict__ w1,
           const float* __restrict__ w2, float* __restrict__ out) {
    __shared__ float w_s[2 * KBLK * WROW];   // [buf][k][64 n]
    __shared__ float s_d[2 * KBLK * SROW];   // [buf][k][128 dup b + pad]
    const int gt = blockIdx.x * NTHR + threadIdx.x;

    // init: zero neuron state; transpose weights (exact fp32 copies)
    for (int i = gt; i < Bn * In; i += NTOT) { g_s1[i] = 0.0f; g_m1[i] = 0.0f; }
    for (int i = gt; i < Bn * Hn; i += NTOT) { g_s2[i] = 0.0f; g_m2[i] = 0.0f; }
    for (int i = gt; i < Bn * On; i += NTOT) { g_s3[i] = 0.0f; g_m3[i] = 0.0f; }
    for (int e = gt; e < In * Hn; e += NTOT) {
        int k = e >> 12, h = e & (Hn - 1);
        g_w1t[e] = w1[(size_t)h * In + k];
    }
    for (int e = gt; e < Hn * On; e += NTOT) {
        int k = e >> 10, o = e & (On - 1);
        g_w2t[e] = w2[(size_t)o * Hn + k];
    }
    gridbar();

    phaseA(x, 0, gt);
    gridbar();

    for (int t = 0; t < Tn; t++) {
        // P1: GEMM2 chunk partials. item = (chunk: bid>>6, h-tile: bid&63)
        {
            const int chunk = blockIdx.x >> 6;
            const int h0 = (blockIdx.x & 63) * 64;
            gemm_chunk<In, Hn>(g_w1t, g_spk1, g_p2[chunk], h0, chunk * 512, w_s, s_d);
        }
        gridbar();
        // P2: layer-2 neurons (combine p2); layer-3 neurons for t-1; layer-1 for t+1
        phaseL2(gt);
        if (t > 0) phaseL3(out, t - 1, gt);
        if (t + 1 < Tn) phaseA(x, t + 1, gt);
        gridbar();
        // P3: GEMM3 chunk partials. item = (chunk: bid>>4, o-tile: bid&15)
        {
            const int chunk = blockIdx.x >> 4;
            const int o0 = (blockIdx.x & 15) * 64;
            gemm_chunk<Hn, On>(g_w2t, g_spk2, g_p3[chunk], o0, chunk * 512, w_s, s_d);
        }
        gridbar();
    }
    phaseL3(out, Tn - 1, gt);
}

extern "C" void kernel_launch(void* const* d_in, const int* in_sizes, int n_in,
                              void* d_out, int out_size) {
    const float* x  = (const float*)d_in[0];   // [512,64,1024]
    const float* w1 = (const float*)d_in[1];   // [4096,1024]
    const float* w2 = (const float*)d_in[2];   // [1024,4096]
    float* out = (float*)d_out;                // [512,64,1024]
    snn_kernel<<<NCTA, NTHR>>>(x, w1, w2, out);
}